// round 7
// baseline (speedup 1.0000x reference)
#include <cuda_runtime.h>
#include <math.h>
#include <float.h>

// ---------------------------------------------------------------------------
// EdgeConv-style GNN block:
//   layer1 factorized over nodes:  pre1(e) = A[tgt] + B[src]
//   layer2 fused per-message GEMM (messages counting-sorted by tgt):
//       z = relu(pre1) @ W2'^T + c2   (BN1 folded)
//   epilogue: run-combined max over relu(z+c2), BN2 applied at flush,
//             atomic float max into agg[tgt]
//   layer3: out = BN3(relu(agg @ W3^T + b3))
// ---------------------------------------------------------------------------

#define C_IN   128
#define C_OUT  256
#define TM     64     // k1/k3 rows per CTA
#define TM2    128    // k2 rows per CTA
#define KC     64     // K chunk
#define NTHR   256
#define SVS    65     // k1/k3 float2 row stride
#define SVS2   66     // k2 float2 row stride (16B-aligned rows)
#define BN_EPS 1e-5f
#define MAXN   20000
#define MAXE   640000
#define MAXM   (MAXE + MAXN)

__host__ __device__ __forceinline__ int prow2(int r) { return r * SVS2 + ((r >> 3) << 1); }
#define PROW128 (128 * SVS2 + 32)   // 8480 float2

// ---- static device scratch -------------------------------------------------
static __device__ __align__(128) float g_AB [(size_t)MAXN * 2 * C_OUT];
static __device__ __align__(128) float g_agg[(size_t)MAXN * C_OUT];
static __device__ __align__(128) float g_Wct[C_IN * 2 * C_OUT];
static __device__ __align__(128) float g_W2t[C_OUT * C_OUT];
static __device__ __align__(128) float g_W3t[C_OUT * C_OUT];
static __device__ __align__(128) float g_c2 [C_OUT];
static __device__ __align__(128) float g_s2 [C_OUT], g_t2[C_OUT];
static __device__ __align__(128) float g_s3 [C_OUT], g_t3[C_OUT];
static __device__ __align__(128) int   g_src[MAXE], g_tgt[MAXE];
static __device__ __align__(128) int   g_osrc[MAXM], g_otgt[MAXM];
static __device__ __align__(128) int   g_cnt[MAXN], g_cur[MAXN];
static __device__ int g_idx64;

// ---- packed fp32x2 FMA ------------------------------------------------------
__device__ __forceinline__ unsigned long long fma2(unsigned long long a,
                                                   unsigned long long b,
                                                   unsigned long long c) {
    unsigned long long d;
    asm("fma.rn.f32x2 %0, %1, %2, %3;" : "=l"(d) : "l"(a), "l"(b), "l"(c));
    return d;
}
__device__ __forceinline__ float2 unpack2(unsigned long long u) {
    float2 f;
    asm("mov.b64 {%0, %1}, %2;" : "=f"(f.x), "=f"(f.y) : "l"(u));
    return f;
}
__device__ __forceinline__ void lds_v2u64(unsigned long long& a, unsigned long long& b,
                                          unsigned int addr) {
    asm volatile("ld.shared.v2.u64 {%0, %1}, [%2];" : "=l"(a), "=l"(b) : "r"(addr));
}

__device__ __forceinline__ void atomicMaxF(float* a, float v) {
    int bits = __float_as_int(v);
    if (bits >= 0) atomicMax((int*)a, bits);
    else           atomicMin((unsigned int*)a, (unsigned int)bits);
}

// ---- k1/k3 shared GEMM inner loop (unchanged, known-good) -------------------
__device__ __forceinline__ void gemm_chunk(const float2* __restrict__ sV2,
                                           const float* __restrict__ sW,
                                           unsigned long long acc[8][4],
                                           int mg, int ng) {
    const float2* vbase = sV2 + mg * 8 * SVS;
    const unsigned long long* wbase =
        reinterpret_cast<const unsigned long long*>(sW + ng * 8);
#pragma unroll 4
    for (int k = 0; k < KC; ++k) {
        unsigned long long w0 = wbase[k * 128 + 0];
        unsigned long long w1 = wbase[k * 128 + 1];
        unsigned long long w2 = wbase[k * 128 + 2];
        unsigned long long w3 = wbase[k * 128 + 3];
#pragma unroll
        for (int i = 0; i < 8; ++i) {
            unsigned long long vv =
                *reinterpret_cast<const unsigned long long*>(vbase + i * SVS + k);
            acc[i][0] = fma2(vv, w0, acc[i][0]);
            acc[i][1] = fma2(vv, w1, acc[i][1]);
            acc[i][2] = fma2(vv, w2, acc[i][2]);
            acc[i][3] = fma2(vv, w3, acc[i][3]);
        }
    }
}

__device__ __forceinline__ void load_w_chunk(float* sW, const float* __restrict__ gW,
                                             int rowStride, int tid) {
    for (int t = tid; t < KC * (C_OUT / 4); t += NTHR) {
        int kk = t >> 6;
        int c4 = t & 63;
        *(float4*)(sW + kk * C_OUT + (c4 << 2)) =
            *(const float4*)(gW + (size_t)kk * rowStride + (c4 << 2));
    }
}

// ---- edge index dtype detection + decode ------------------------------------
__global__ void detect_idx(const int* __restrict__ p) {
    if (threadIdx.x == 0) {
        int is64 = 1;
        for (int i = 0; i < 64; ++i)
            if (p[2 * i + 1] != 0) { is64 = 0; break; }
        g_idx64 = is64;
    }
}

__global__ void decode_idx(const void* __restrict__ idxRaw, long long E2, int Nn) {
    long long i = (long long)blockIdx.x * blockDim.x + threadIdx.x;
    if (i >= E2) return;
    int v;
    if (g_idx64) v = (int)((const long long*)idxRaw)[i];
    else         v = ((const int*)idxRaw)[i];
    if (v < 0) v = 0;
    if (v >= Nn) v = Nn - 1;
    long long E = E2 >> 1;
    if (i < E) g_src[i] = v;
    else       g_tgt[i - E] = v;
}

// ---- counting sort by tgt ----------------------------------------------------
__global__ void hist_zero(int Nn) {
    int i = blockIdx.x * blockDim.x + threadIdx.x;
    if (i < Nn) g_cnt[i] = 0;
}
__global__ void hist_tgt(long long E) {
    long long m = (long long)blockIdx.x * blockDim.x + threadIdx.x;
    if (m < E) atomicAdd(&g_cnt[g_tgt[m]], 1);
}
__global__ void scan_base(int Nn) {     // single CTA, 256 threads
    __shared__ int part[256];
    int th = threadIdx.x;
    int chunk = (Nn + 255) >> 8;
    int lo = th * chunk, hi = lo + chunk; if (hi > Nn) hi = Nn; if (lo > Nn) lo = Nn;
    int s = 0;
    for (int n = lo; n < hi; ++n) s += g_cnt[n] + 1;   // +1 self loop
    part[th] = s;
    __syncthreads();
    if (th == 0) {
        int r = 0;
        for (int i = 0; i < 256; ++i) { int t = part[i]; part[i] = r; r += t; }
    }
    __syncthreads();
    int run = part[th];
    for (int n = lo; n < hi; ++n) { g_cur[n] = run; run += g_cnt[n] + 1; }
}
__global__ void scatter_edges(long long E) {
    long long m = (long long)blockIdx.x * blockDim.x + threadIdx.x;
    if (m >= E) return;
    int t = g_tgt[m];
    int p = atomicAdd(&g_cur[t], 1);
    g_osrc[p] = g_src[m];
    g_otgt[p] = t;
}
__global__ void scatter_loops(int Nn) {
    int n = blockIdx.x * blockDim.x + threadIdx.x;
    if (n >= Nn) return;
    int p = atomicAdd(&g_cur[n], 1);
    g_osrc[p] = n;
    g_otgt[p] = n;
}

// ---- prep kernels -----------------------------------------------------------
__global__ void prep_bn(const float* g1, const float* be1, const float* m1, const float* v1,
                        const float* W2, const float* b2,
                        const float* g2, const float* be2, const float* m2, const float* v2,
                        const float* g3, const float* be3, const float* m3, const float* v3) {
    int c = threadIdx.x;
    float s2 = g2[c] * rsqrtf(v2[c] + BN_EPS);
    g_s2[c] = s2;  g_t2[c] = be2[c] - m2[c] * s2;
    float s3 = g3[c] * rsqrtf(v3[c] + BN_EPS);
    g_s3[c] = s3;  g_t3[c] = be3[c] - m3[c] * s3;
    float acc = b2[c];
    for (int k = 0; k < C_OUT; ++k) {
        float s1 = g1[k] * rsqrtf(v1[k] + BN_EPS);
        float t1 = be1[k] - m1[k] * s1;
        acc += W2[c * C_OUT + k] * t1;
    }
    g_c2[c] = acc;
}

__global__ void prep_w(const float* W1, const float* W2, const float* W3,
                       const float* g1, const float* v1) {
    int i = blockIdx.x * blockDim.x + threadIdx.x;
    if (i < C_IN * 2 * C_OUT) {
        int k = i / (2 * C_OUT), j = i % (2 * C_OUT);
        float val;
        if (j < C_OUT)
            val = W1[j * (2 * C_IN) + k] - W1[j * (2 * C_IN) + C_IN + k];
        else
            val = W1[(j - C_OUT) * (2 * C_IN) + C_IN + k];
        g_Wct[i] = val;
    }
    if (i < C_OUT * C_OUT) {
        int k = i / C_OUT, n = i % C_OUT;
        float s1 = g1[k] * rsqrtf(v1[k] + BN_EPS);
        g_W2t[i] = W2[n * C_OUT + k] * s1;
        g_W3t[i] = W3[n * C_OUT + k];
    }
}

__global__ void init_agg(int total) {
    int i = blockIdx.x * blockDim.x + threadIdx.x;
    if (i < total) g_agg[i] = -FLT_MAX;
}

// ---- kernel 1: node GEMM -> A|B table ---------------------------------------
__global__ void __launch_bounds__(NTHR, 2)
k1_node_gemm(const float* __restrict__ x, const float* __restrict__ b1, int Nn) {
    extern __shared__ float sh[];
    float2* sV2 = (float2*)sh;
    float*  sW  = sh + TM * SVS * 2;
    int tid = threadIdx.x;
    int mg = tid >> 5, ng = tid & 31;
    int row = tid >> 2, q = tid & 3;
    int m0 = blockIdx.x * TM;
    int jh = blockIdx.y;
    int node = m0 + row; if (node >= Nn) node = Nn - 1;

    unsigned long long acc[8][4];
#pragma unroll
    for (int i = 0; i < 8; ++i)
#pragma unroll
        for (int p = 0; p < 4; ++p) acc[i][p] = 0ull;

    for (int kc = 0; kc < C_IN; kc += KC) {
        load_w_chunk(sW, g_Wct + (size_t)kc * (2 * C_OUT) + jh * C_OUT, 2 * C_OUT, tid);
        const float4* xr = (const float4*)(x + (size_t)node * C_IN + kc) + q * 4;
        float2* d = sV2 + row * SVS + q * 16;
#pragma unroll
        for (int j = 0; j < 4; ++j) {
            float4 v = xr[j];
            d[j * 4 + 0] = make_float2(v.x, v.x);
            d[j * 4 + 1] = make_float2(v.y, v.y);
            d[j * 4 + 2] = make_float2(v.z, v.z);
            d[j * 4 + 3] = make_float2(v.w, v.w);
        }
        __syncthreads();
        gemm_chunk(sV2, sW, acc, mg, ng);
        __syncthreads();
    }

    int n0 = ng * 8;
#pragma unroll
    for (int i = 0; i < 8; ++i) {
        int nd = m0 + mg * 8 + i;
        if (nd >= Nn) break;
        float* dst = g_AB + (size_t)nd * (2 * C_OUT) + jh * C_OUT + n0;
#pragma unroll
        for (int p = 0; p < 4; ++p) {
            float2 z = unpack2(acc[i][p]);
            if (jh == 0) {
                z.x += __ldg(&b1[n0 + 2 * p]);
                z.y += __ldg(&b1[n0 + 2 * p + 1]);
            }
            dst[2 * p]     = z.x;
            dst[2 * p + 1] = z.y;
        }
    }
}

// ---- kernel 2: fused sorted-message GEMM + run-combined segment max ---------
__global__ void __launch_bounds__(NTHR, 1)
k2_edge_gemm(long long EN) {
    extern __shared__ float sh[];
    float2* sV2 = (float2*)sh;                 // PROW128 float2
    float*  sW  = sh + PROW128 * 2;            // KC * 256 floats
    __shared__ int sSrc[TM2], sTgt[TM2];

    int tid = threadIdx.x;
    long long m0 = (long long)blockIdx.x * TM2;
    if (tid < TM2) {
        long long m = m0 + tid;
        int s = 0, t = -1;
        if (m < EN) { s = g_osrc[m]; t = g_otgt[m]; }
        sSrc[tid] = s;  sTgt[tid] = t;
    }
    __syncthreads();

    int lane = tid & 31, warp = tid >> 5;
    int rg   = lane >> 4;                      // row group 0/1
    int c0   = (lane & 15) << 4;               // 16-col base
    int wrow = warp * 16 + rg * 8;             // this lane's first row

    unsigned svBase = (unsigned)__cvta_generic_to_shared(sV2);
    unsigned swBase = (unsigned)__cvta_generic_to_shared(sW);
    unsigned vAddr  = svBase + (unsigned)(prow2(wrow) * 8);
    unsigned wAddr  = swBase + (unsigned)(c0 * 4);

    // staging mapping: 2 threads per row, 32 k's each
    int srow = tid >> 1, soff = (tid & 1) * 32;
    int stgt = sTgt[srow]; if (stgt < 0) stgt = 0;
    int ssrc = sSrc[srow];
    const float* Arow = g_AB + (size_t)stgt * (2 * C_OUT);
    const float* Brow = g_AB + (size_t)ssrc * (2 * C_OUT) + C_OUT;
    float2* dstg = sV2 + prow2(srow) + soff;

    unsigned long long acc[8][8];
#pragma unroll
    for (int i = 0; i < 8; ++i)
#pragma unroll
        for (int p = 0; p < 8; ++p) acc[i][p] = 0ull;

    for (int kc = 0; kc < C_OUT; kc += KC) {
        load_w_chunk(sW, g_W2t + (size_t)kc * C_OUT, C_OUT, tid);
        const float4* ar = (const float4*)(Arow + kc + soff);
        const float4* br = (const float4*)(Brow + kc + soff);
#pragma unroll
        for (int j = 0; j < 8; ++j) {
            float4 a = ar[j], b = br[j];
            float vx = fmaxf(a.x + b.x, 0.0f);
            float vy = fmaxf(a.y + b.y, 0.0f);
            float vz = fmaxf(a.z + b.z, 0.0f);
            float vw = fmaxf(a.w + b.w, 0.0f);
            *(float4*)(dstg + j * 4)     = make_float4(vx, vx, vy, vy);
            *(float4*)(dstg + j * 4 + 2) = make_float4(vz, vz, vw, vw);
        }
        __syncthreads();

#pragma unroll 2
        for (int k = 0; k < KC; k += 2) {
            unsigned long long wa[8], wb[8];
            unsigned wk = wAddr + (unsigned)(k * 1024);
#pragma unroll
            for (int j = 0; j < 4; ++j) lds_v2u64(wa[2 * j], wa[2 * j + 1], wk + j * 16);
#pragma unroll
            for (int j = 0; j < 4; ++j) lds_v2u64(wb[2 * j], wb[2 * j + 1], wk + 1024 + j * 16);
#pragma unroll
            for (int i = 0; i < 8; ++i) {
                unsigned long long va, vb;
                lds_v2u64(va, vb, vAddr + (unsigned)(i * (SVS2 * 8) + k * 8));
#pragma unroll
                for (int p = 0; p < 8; ++p) acc[i][p] = fma2(va, wa[p], acc[i][p]);
#pragma unroll
                for (int p = 0; p < 8; ++p) acc[i][p] = fma2(vb, wb[p], acc[i][p]);
            }
        }
        __syncthreads();
    }

    // ---- epilogue: run-combined max (relu part), BN2 at flush ----------------
    float c2v[16];
#pragma unroll
    for (int j = 0; j < 16; ++j) c2v[j] = __ldg(&g_c2[c0 + j]);

    float rmax[16], rmin[16];
#pragma unroll
    for (int j = 0; j < 16; ++j) { rmax[j] = -FLT_MAX; rmin[j] = FLT_MAX; }

    int cur = sTgt[wrow];
#pragma unroll
    for (int i = 0; i < 8; ++i) {
        int t = sTgt[wrow + i];
        if (t != cur) {
            if (cur >= 0) {
                float* dst = g_agg + (size_t)cur * C_OUT + c0;
#pragma unroll
                for (int j = 0; j < 16; ++j) {
                    float s2 = __ldg(&g_s2[c0 + j]);
                    float t2 = __ldg(&g_t2[c0 + j]);
                    float cand = (s2 >= 0.0f ? rmax[j] : rmin[j]) * s2 + t2;
                    atomicMaxF(dst + j, cand);
                }
            }
#pragma unroll
            for (int j = 0; j < 16; ++j) { rmax[j] = -FLT_MAX; rmin[j] = FLT_MAX; }
            cur = t;
        }
#pragma unroll
        for (int p = 0; p < 8; ++p) {
            float2 z = unpack2(acc[i][p]);
            float u0 = fmaxf(z.x + c2v[2 * p],     0.0f);
            float u1 = fmaxf(z.y + c2v[2 * p + 1], 0.0f);
            rmax[2 * p]     = fmaxf(rmax[2 * p],     u0);
            rmin[2 * p]     = fminf(rmin[2 * p],     u0);
            rmax[2 * p + 1] = fmaxf(rmax[2 * p + 1], u1);
            rmin[2 * p + 1] = fminf(rmin[2 * p + 1], u1);
        }
    }
    if (cur >= 0) {
        float* dst = g_agg + (size_t)cur * C_OUT + c0;
#pragma unroll
        for (int j = 0; j < 16; ++j) {
            float s2 = __ldg(&g_s2[c0 + j]);
            float t2 = __ldg(&g_t2[c0 + j]);
            float cand = (s2 >= 0.0f ? rmax[j] : rmin[j]) * s2 + t2;
            atomicMaxF(dst + j, cand);
        }
    }
}

// ---- kernel 3: out = BN3(relu(agg @ W3^T + b3)) -----------------------------
__global__ void __launch_bounds__(NTHR, 2)
k3_out_gemm(const float* __restrict__ b3, float* __restrict__ out, int Nn) {
    extern __shared__ float sh[];
    float2* sV2 = (float2*)sh;
    float*  sW  = sh + TM * SVS * 2;
    int tid = threadIdx.x;
    int mg = tid >> 5, ng = tid & 31;
    int row = tid >> 2, q = tid & 3;
    int m0 = blockIdx.x * TM;
    int node = m0 + row; if (node >= Nn) node = Nn - 1;

    unsigned long long acc[8][4];
#pragma unroll
    for (int i = 0; i < 8; ++i)
#pragma unroll
        for (int p = 0; p < 4; ++p) acc[i][p] = 0ull;

    const float* Ar = g_agg + (size_t)node * C_OUT;
    for (int kc = 0; kc < C_OUT; kc += KC) {
        load_w_chunk(sW, g_W3t + (size_t)kc * C_OUT, C_OUT, tid);
        const float4* ar = (const float4*)(Ar + kc) + q * 4;
        float2* d = sV2 + row * SVS + q * 16;
#pragma unroll
        for (int j = 0; j < 4; ++j) {
            float4 v = ar[j];
            d[j * 4 + 0] = make_float2(v.x, v.x);
            d[j * 4 + 1] = make_float2(v.y, v.y);
            d[j * 4 + 2] = make_float2(v.z, v.z);
            d[j * 4 + 3] = make_float2(v.w, v.w);
        }
        __syncthreads();
        gemm_chunk(sV2, sW, acc, mg, ng);
        __syncthreads();
    }

    int n0 = ng * 8;
    float b3v[8], s3v[8], t3v[8];
#pragma unroll
    for (int u = 0; u < 8; ++u) {
        b3v[u] = __ldg(&b3[n0 + u]);
        s3v[u] = __ldg(&g_s3[n0 + u]);
        t3v[u] = __ldg(&g_t3[n0 + u]);
    }
#pragma unroll
    for (int i = 0; i < 8; ++i) {
        int nd = m0 + mg * 8 + i;
        if (nd >= Nn) break;
        float* dst = out + (size_t)nd * C_OUT + n0;
#pragma unroll
        for (int p = 0; p < 4; ++p) {
            float2 z = unpack2(acc[i][p]);
            dst[2 * p]     = fmaxf(z.x + b3v[2 * p],     0.0f) * s3v[2 * p]     + t3v[2 * p];
            dst[2 * p + 1] = fmaxf(z.y + b3v[2 * p + 1], 0.0f) * s3v[2 * p + 1] + t3v[2 * p + 1];
        }
    }
}

// ---------------------------------------------------------------------------
extern "C" void kernel_launch(void* const* d_in, const int* in_sizes, int n_in,
                              void* d_out, int out_size) {
    const float* x   = (const float*)d_in[0];
    const void*  idx = (const void*)d_in[1];
    const float* W1 = (const float*)d_in[2];  const float* b1 = (const float*)d_in[3];
    const float* g1 = (const float*)d_in[4];  const float* be1= (const float*)d_in[5];
    const float* m1 = (const float*)d_in[6];  const float* v1 = (const float*)d_in[7];
    const float* W2 = (const float*)d_in[8];  const float* b2 = (const float*)d_in[9];
    const float* g2 = (const float*)d_in[10]; const float* be2= (const float*)d_in[11];
    const float* m2 = (const float*)d_in[12]; const float* v2 = (const float*)d_in[13];
    const float* W3 = (const float*)d_in[14]; const float* b3 = (const float*)d_in[15];
    const float* g3 = (const float*)d_in[16]; const float* be3= (const float*)d_in[17];
    const float* m3 = (const float*)d_in[18]; const float* v3 = (const float*)d_in[19];
    float* out = (float*)d_out;

    int Nn = in_sizes[0] / C_IN;
    long long E2 = (long long)in_sizes[1];
    long long E  = E2 >> 1;
    long long EN = E + Nn;

    size_t shmem13 = (size_t)TM * SVS * sizeof(float2) + (size_t)KC * C_OUT * sizeof(float);
    size_t shmem2  = (size_t)PROW128 * sizeof(float2) + (size_t)KC * C_OUT * sizeof(float);
    cudaFuncSetAttribute(k1_node_gemm, cudaFuncAttributeMaxDynamicSharedMemorySize, (int)shmem13);
    cudaFuncSetAttribute(k2_edge_gemm, cudaFuncAttributeMaxDynamicSharedMemorySize, (int)shmem2);
    cudaFuncSetAttribute(k3_out_gemm,  cudaFuncAttributeMaxDynamicSharedMemorySize, (int)shmem13);

    // decode + counting sort by tgt
    detect_idx<<<1, 32>>>((const int*)idx);
    decode_idx<<<(int)((E2 + 255) / 256), 256>>>(idx, E2, Nn);
    hist_zero<<<(Nn + 255) / 256, 256>>>(Nn);
    hist_tgt<<<(int)((E + 255) / 256), 256>>>(E);
    scan_base<<<1, 256>>>(Nn);
    scatter_edges<<<(int)((E + 255) / 256), 256>>>(E);
    scatter_loops<<<(Nn + 255) / 256, 256>>>(Nn);

    prep_bn<<<1, C_OUT>>>(g1, be1, m1, v1, W2, b2, g2, be2, m2, v2, g3, be3, m3, v3);
    prep_w<<<(C_IN * 2 * C_OUT + 255) / 256, 256>>>(W1, W2, W3, g1, v1);

    int total = Nn * C_OUT;
    init_agg<<<(total + 255) / 256, 256>>>(total);

    dim3 grid1((Nn + TM - 1) / TM, 2);
    k1_node_gemm<<<grid1, NTHR, shmem13>>>(x, b1, Nn);

    int nblk2 = (int)((EN + TM2 - 1) / TM2);
    k2_edge_gemm<<<nblk2, NTHR, shmem2>>>(EN);

    k3_out_gemm<<<(Nn + TM - 1) / TM, NTHR, shmem13>>>(b3, out, Nn);
}

// round 8
// speedup vs baseline: 1.0003x; 1.0003x over previous
#include <cuda_runtime.h>
#include <math.h>
#include <float.h>

// ---------------------------------------------------------------------------
// EdgeConv-style GNN block:
//   layer1 factorized over nodes:  pre1(e) = A[tgt] + B[src]
//   layer2 fused per-message GEMM (messages counting-sorted by tgt):
//       z = relu(pre1) @ W2'^T + c2   (BN1 folded)
//   epilogue: run-combined max over relu(z+c2), BN2 applied at flush,
//             atomic float max into agg[tgt]
//   layer3: out = BN3(relu(agg @ W3^T + b3))
// ---------------------------------------------------------------------------

#define C_IN   128
#define C_OUT  256
#define TM     64     // k1/k3 rows per CTA
#define TM2    128    // k2 rows per CTA
#define KC     64     // K chunk
#define NTHR   256
#define SVS    65     // k1/k3 float2 row stride
#define SVS2   66     // k2 float2 row stride (16B-aligned rows)
#define BN_EPS 1e-5f
#define MAXN   20000
#define MAXE   640000
#define MAXM   (MAXE + MAXN)

__host__ __device__ __forceinline__ int prow2(int r) { return r * SVS2 + ((r >> 3) << 1); }
#define PROW128 (128 * SVS2 + 32)   // 8480 float2

// ---- static device scratch -------------------------------------------------
static __device__ __align__(128) float g_AB [(size_t)MAXN * 2 * C_OUT];
static __device__ __align__(128) float g_agg[(size_t)MAXN * C_OUT];
static __device__ __align__(128) float g_Wct[C_IN * 2 * C_OUT];
static __device__ __align__(128) float g_W2t[C_OUT * C_OUT];
static __device__ __align__(128) float g_W3t[C_OUT * C_OUT];
static __device__ __align__(128) float g_c2 [C_OUT];
static __device__ __align__(128) float g_s2 [C_OUT], g_t2[C_OUT];
static __device__ __align__(128) float g_s3 [C_OUT], g_t3[C_OUT];
static __device__ __align__(128) int   g_src[MAXE], g_tgt[MAXE];
static __device__ __align__(128) int   g_osrc[MAXM], g_otgt[MAXM];
static __device__ __align__(128) int   g_cnt[MAXN], g_cur[MAXN];
static __device__ int g_idx64;

// ---- packed fp32x2 FMA ------------------------------------------------------
__device__ __forceinline__ unsigned long long fma2(unsigned long long a,
                                                   unsigned long long b,
                                                   unsigned long long c) {
    unsigned long long d;
    asm("fma.rn.f32x2 %0, %1, %2, %3;" : "=l"(d) : "l"(a), "l"(b), "l"(c));
    return d;
}
__device__ __forceinline__ float2 unpack2(unsigned long long u) {
    float2 f;
    asm("mov.b64 {%0, %1}, %2;" : "=f"(f.x), "=f"(f.y) : "l"(u));
    return f;
}
__device__ __forceinline__ void lds_v2u64(unsigned long long& a, unsigned long long& b,
                                          unsigned int addr) {
    asm volatile("ld.shared.v2.u64 {%0, %1}, [%2];" : "=l"(a), "=l"(b) : "r"(addr));
}

__device__ __forceinline__ void atomicMaxF(float* a, float v) {
    int bits = __float_as_int(v);
    if (bits >= 0) atomicMax((int*)a, bits);
    else           atomicMin((unsigned int*)a, (unsigned int)bits);
}

// ---- k1/k3 shared GEMM inner loop (unchanged, known-good) -------------------
__device__ __forceinline__ void gemm_chunk(const float2* __restrict__ sV2,
                                           const float* __restrict__ sW,
                                           unsigned long long acc[8][4],
                                           int mg, int ng) {
    const float2* vbase = sV2 + mg * 8 * SVS;
    const unsigned long long* wbase =
        reinterpret_cast<const unsigned long long*>(sW + ng * 8);
#pragma unroll 4
    for (int k = 0; k < KC; ++k) {
        unsigned long long w0 = wbase[k * 128 + 0];
        unsigned long long w1 = wbase[k * 128 + 1];
        unsigned long long w2 = wbase[k * 128 + 2];
        unsigned long long w3 = wbase[k * 128 + 3];
#pragma unroll
        for (int i = 0; i < 8; ++i) {
            unsigned long long vv =
                *reinterpret_cast<const unsigned long long*>(vbase + i * SVS + k);
            acc[i][0] = fma2(vv, w0, acc[i][0]);
            acc[i][1] = fma2(vv, w1, acc[i][1]);
            acc[i][2] = fma2(vv, w2, acc[i][2]);
            acc[i][3] = fma2(vv, w3, acc[i][3]);
        }
    }
}

__device__ __forceinline__ void load_w_chunk(float* sW, const float* __restrict__ gW,
                                             int rowStride, int tid) {
    for (int t = tid; t < KC * (C_OUT / 4); t += NTHR) {
        int kk = t >> 6;
        int c4 = t & 63;
        *(float4*)(sW + kk * C_OUT + (c4 << 2)) =
            *(const float4*)(gW + (size_t)kk * rowStride + (c4 << 2));
    }
}

// ---- edge index dtype detection + decode ------------------------------------
__global__ void detect_idx(const int* __restrict__ p) {
    if (threadIdx.x == 0) {
        int is64 = 1;
        for (int i = 0; i < 64; ++i)
            if (p[2 * i + 1] != 0) { is64 = 0; break; }
        g_idx64 = is64;
    }
}

__global__ void decode_idx(const void* __restrict__ idxRaw, long long E2, int Nn) {
    long long i = (long long)blockIdx.x * blockDim.x + threadIdx.x;
    if (i >= E2) return;
    int v;
    if (g_idx64) v = (int)((const long long*)idxRaw)[i];
    else         v = ((const int*)idxRaw)[i];
    if (v < 0) v = 0;
    if (v >= Nn) v = Nn - 1;
    long long E = E2 >> 1;
    if (i < E) g_src[i] = v;
    else       g_tgt[i - E] = v;
}

// ---- counting sort by tgt ----------------------------------------------------
__global__ void hist_zero(int Nn) {
    int i = blockIdx.x * blockDim.x + threadIdx.x;
    if (i < Nn) g_cnt[i] = 0;
}
__global__ void hist_tgt(long long E) {
    long long m = (long long)blockIdx.x * blockDim.x + threadIdx.x;
    if (m < E) atomicAdd(&g_cnt[g_tgt[m]], 1);
}
__global__ void scan_base(int Nn) {     // single CTA, 256 threads
    __shared__ int part[256];
    int th = threadIdx.x;
    int chunk = (Nn + 255) >> 8;
    int lo = th * chunk, hi = lo + chunk; if (hi > Nn) hi = Nn; if (lo > Nn) lo = Nn;
    int s = 0;
    for (int n = lo; n < hi; ++n) s += g_cnt[n] + 1;   // +1 self loop
    part[th] = s;
    __syncthreads();
    if (th == 0) {
        int r = 0;
        for (int i = 0; i < 256; ++i) { int t = part[i]; part[i] = r; r += t; }
    }
    __syncthreads();
    int run = part[th];
    for (int n = lo; n < hi; ++n) { g_cur[n] = run; run += g_cnt[n] + 1; }
}
__global__ void scatter_edges(long long E) {
    long long m = (long long)blockIdx.x * blockDim.x + threadIdx.x;
    if (m >= E) return;
    int t = g_tgt[m];
    int p = atomicAdd(&g_cur[t], 1);
    g_osrc[p] = g_src[m];
    g_otgt[p] = t;
}
__global__ void scatter_loops(int Nn) {
    int n = blockIdx.x * blockDim.x + threadIdx.x;
    if (n >= Nn) return;
    int p = atomicAdd(&g_cur[n], 1);
    g_osrc[p] = n;
    g_otgt[p] = n;
}

// ---- prep kernels -----------------------------------------------------------
__global__ void prep_bn(const float* g1, const float* be1, const float* m1, const float* v1,
                        const float* W2, const float* b2,
                        const float* g2, const float* be2, const float* m2, const float* v2,
                        const float* g3, const float* be3, const float* m3, const float* v3) {
    int c = threadIdx.x;
    float s2 = g2[c] * rsqrtf(v2[c] + BN_EPS);
    g_s2[c] = s2;  g_t2[c] = be2[c] - m2[c] * s2;
    float s3 = g3[c] * rsqrtf(v3[c] + BN_EPS);
    g_s3[c] = s3;  g_t3[c] = be3[c] - m3[c] * s3;
    float acc = b2[c];
    for (int k = 0; k < C_OUT; ++k) {
        float s1 = g1[k] * rsqrtf(v1[k] + BN_EPS);
        float t1 = be1[k] - m1[k] * s1;
        acc += W2[c * C_OUT + k] * t1;
    }
    g_c2[c] = acc;
}

__global__ void prep_w(const float* W1, const float* W2, const float* W3,
                       const float* g1, const float* v1) {
    int i = blockIdx.x * blockDim.x + threadIdx.x;
    if (i < C_IN * 2 * C_OUT) {
        int k = i / (2 * C_OUT), j = i % (2 * C_OUT);
        float val;
        if (j < C_OUT)
            val = W1[j * (2 * C_IN) + k] - W1[j * (2 * C_IN) + C_IN + k];
        else
            val = W1[(j - C_OUT) * (2 * C_IN) + C_IN + k];
        g_Wct[i] = val;
    }
    if (i < C_OUT * C_OUT) {
        int k = i / C_OUT, n = i % C_OUT;
        float s1 = g1[k] * rsqrtf(v1[k] + BN_EPS);
        g_W2t[i] = W2[n * C_OUT + k] * s1;
        g_W3t[i] = W3[n * C_OUT + k];
    }
}

__global__ void init_agg(int total) {
    int i = blockIdx.x * blockDim.x + threadIdx.x;
    if (i < total) g_agg[i] = -FLT_MAX;
}

// ---- kernel 1: node GEMM -> A|B table ---------------------------------------
__global__ void __launch_bounds__(NTHR, 2)
k1_node_gemm(const float* __restrict__ x, const float* __restrict__ b1, int Nn) {
    extern __shared__ float sh[];
    float2* sV2 = (float2*)sh;
    float*  sW  = sh + TM * SVS * 2;
    int tid = threadIdx.x;
    int mg = tid >> 5, ng = tid & 31;
    int row = tid >> 2, q = tid & 3;
    int m0 = blockIdx.x * TM;
    int jh = blockIdx.y;
    int node = m0 + row; if (node >= Nn) node = Nn - 1;

    unsigned long long acc[8][4];
#pragma unroll
    for (int i = 0; i < 8; ++i)
#pragma unroll
        for (int p = 0; p < 4; ++p) acc[i][p] = 0ull;

    for (int kc = 0; kc < C_IN; kc += KC) {
        load_w_chunk(sW, g_Wct + (size_t)kc * (2 * C_OUT) + jh * C_OUT, 2 * C_OUT, tid);
        const float4* xr = (const float4*)(x + (size_t)node * C_IN + kc) + q * 4;
        float2* d = sV2 + row * SVS + q * 16;
#pragma unroll
        for (int j = 0; j < 4; ++j) {
            float4 v = xr[j];
            d[j * 4 + 0] = make_float2(v.x, v.x);
            d[j * 4 + 1] = make_float2(v.y, v.y);
            d[j * 4 + 2] = make_float2(v.z, v.z);
            d[j * 4 + 3] = make_float2(v.w, v.w);
        }
        __syncthreads();
        gemm_chunk(sV2, sW, acc, mg, ng);
        __syncthreads();
    }

    int n0 = ng * 8;
#pragma unroll
    for (int i = 0; i < 8; ++i) {
        int nd = m0 + mg * 8 + i;
        if (nd >= Nn) break;
        float* dst = g_AB + (size_t)nd * (2 * C_OUT) + jh * C_OUT + n0;
#pragma unroll
        for (int p = 0; p < 4; ++p) {
            float2 z = unpack2(acc[i][p]);
            if (jh == 0) {
                z.x += __ldg(&b1[n0 + 2 * p]);
                z.y += __ldg(&b1[n0 + 2 * p + 1]);
            }
            dst[2 * p]     = z.x;
            dst[2 * p + 1] = z.y;
        }
    }
}

// ---- kernel 2: fused sorted-message GEMM + run-combined segment max ---------
__global__ void __launch_bounds__(NTHR, 1)
k2_edge_gemm(long long EN) {
    extern __shared__ float sh[];
    float2* sV2 = (float2*)sh;                 // PROW128 float2
    float*  sW  = sh + PROW128 * 2;            // KC * 256 floats
    __shared__ int sSrc[TM2], sTgt[TM2];

    int tid = threadIdx.x;
    long long m0 = (long long)blockIdx.x * TM2;
    if (tid < TM2) {
        long long m = m0 + tid;
        int s = 0, t = -1;
        if (m < EN) { s = g_osrc[m]; t = g_otgt[m]; }
        sSrc[tid] = s;  sTgt[tid] = t;
    }
    __syncthreads();

    int lane = tid & 31, warp = tid >> 5;
    int rg   = lane >> 4;                      // row group 0/1
    int c0   = (lane & 15) << 4;               // 16-col base
    int wrow = warp * 16 + rg * 8;             // this lane's first row

    unsigned svBase = (unsigned)__cvta_generic_to_shared(sV2);
    unsigned swBase = (unsigned)__cvta_generic_to_shared(sW);
    unsigned vAddr  = svBase + (unsigned)(prow2(wrow) * 8);
    unsigned wAddr  = swBase + (unsigned)(c0 * 4);

    // staging mapping: 2 threads per row, 32 k's each
    int srow = tid >> 1, soff = (tid & 1) * 32;
    int stgt = sTgt[srow]; if (stgt < 0) stgt = 0;
    int ssrc = sSrc[srow];
    const float* Arow = g_AB + (size_t)stgt * (2 * C_OUT);
    const float* Brow = g_AB + (size_t)ssrc * (2 * C_OUT) + C_OUT;
    float2* dstg = sV2 + prow2(srow) + soff;

    unsigned long long acc[8][8];
#pragma unroll
    for (int i = 0; i < 8; ++i)
#pragma unroll
        for (int p = 0; p < 8; ++p) acc[i][p] = 0ull;

    for (int kc = 0; kc < C_OUT; kc += KC) {
        load_w_chunk(sW, g_W2t + (size_t)kc * C_OUT, C_OUT, tid);
        const float4* ar = (const float4*)(Arow + kc + soff);
        const float4* br = (const float4*)(Brow + kc + soff);
#pragma unroll
        for (int j = 0; j < 8; ++j) {
            float4 a = ar[j], b = br[j];
            float vx = fmaxf(a.x + b.x, 0.0f);
            float vy = fmaxf(a.y + b.y, 0.0f);
            float vz = fmaxf(a.z + b.z, 0.0f);
            float vw = fmaxf(a.w + b.w, 0.0f);
            *(float4*)(dstg + j * 4)     = make_float4(vx, vx, vy, vy);
            *(float4*)(dstg + j * 4 + 2) = make_float4(vz, vz, vw, vw);
        }
        __syncthreads();

#pragma unroll 2
        for (int k = 0; k < KC; k += 2) {
            unsigned long long wa[8], wb[8];
            unsigned wk = wAddr + (unsigned)(k * 1024);
#pragma unroll
            for (int j = 0; j < 4; ++j) lds_v2u64(wa[2 * j], wa[2 * j + 1], wk + j * 16);
#pragma unroll
            for (int j = 0; j < 4; ++j) lds_v2u64(wb[2 * j], wb[2 * j + 1], wk + 1024 + j * 16);
#pragma unroll
            for (int i = 0; i < 8; ++i) {
                unsigned long long va, vb;
                lds_v2u64(va, vb, vAddr + (unsigned)(i * (SVS2 * 8) + k * 8));
#pragma unroll
                for (int p = 0; p < 8; ++p) acc[i][p] = fma2(va, wa[p], acc[i][p]);
#pragma unroll
                for (int p = 0; p < 8; ++p) acc[i][p] = fma2(vb, wb[p], acc[i][p]);
            }
        }
        __syncthreads();
    }

    // ---- epilogue: run-combined max (relu part), BN2 at flush ----------------
    float c2v[16];
#pragma unroll
    for (int j = 0; j < 16; ++j) c2v[j] = __ldg(&g_c2[c0 + j]);

    float rmax[16], rmin[16];
#pragma unroll
    for (int j = 0; j < 16; ++j) { rmax[j] = -FLT_MAX; rmin[j] = FLT_MAX; }

    int cur = sTgt[wrow];
#pragma unroll
    for (int i = 0; i < 8; ++i) {
        int t = sTgt[wrow + i];
        if (t != cur) {
            if (cur >= 0) {
                float* dst = g_agg + (size_t)cur * C_OUT + c0;
#pragma unroll
                for (int j = 0; j < 16; ++j) {
                    float s2 = __ldg(&g_s2[c0 + j]);
                    float t2 = __ldg(&g_t2[c0 + j]);
                    float cand = (s2 >= 0.0f ? rmax[j] : rmin[j]) * s2 + t2;
                    atomicMaxF(dst + j, cand);
                }
            }
#pragma unroll
            for (int j = 0; j < 16; ++j) { rmax[j] = -FLT_MAX; rmin[j] = FLT_MAX; }
            cur = t;
        }
#pragma unroll
        for (int p = 0; p < 8; ++p) {
            float2 z = unpack2(acc[i][p]);
            float u0 = fmaxf(z.x + c2v[2 * p],     0.0f);
            float u1 = fmaxf(z.y + c2v[2 * p + 1], 0.0f);
            rmax[2 * p]     = fmaxf(rmax[2 * p],     u0);
            rmin[2 * p]     = fminf(rmin[2 * p],     u0);
            rmax[2 * p + 1] = fmaxf(rmax[2 * p + 1], u1);
            rmin[2 * p + 1] = fminf(rmin[2 * p + 1], u1);
        }
    }
    if (cur >= 0) {
        float* dst = g_agg + (size_t)cur * C_OUT + c0;
#pragma unroll
        for (int j = 0; j < 16; ++j) {
            float s2 = __ldg(&g_s2[c0 + j]);
            float t2 = __ldg(&g_t2[c0 + j]);
            float cand = (s2 >= 0.0f ? rmax[j] : rmin[j]) * s2 + t2;
            atomicMaxF(dst + j, cand);
        }
    }
}

// ---- kernel 3: out = BN3(relu(agg @ W3^T + b3)) -----------------------------
__global__ void __launch_bounds__(NTHR, 2)
k3_out_gemm(const float* __restrict__ b3, float* __restrict__ out, int Nn) {
    extern __shared__ float sh[];
    float2* sV2 = (float2*)sh;
    float*  sW  = sh + TM * SVS * 2;
    int tid = threadIdx.x;
    int mg = tid >> 5, ng = tid & 31;
    int row = tid >> 2, q = tid & 3;
    int m0 = blockIdx.x * TM;
    int node = m0 + row; if (node >= Nn) node = Nn - 1;

    unsigned long long acc[8][4];
#pragma unroll
    for (int i = 0; i < 8; ++i)
#pragma unroll
        for (int p = 0; p < 4; ++p) acc[i][p] = 0ull;

    const float* Ar = g_agg + (size_t)node * C_OUT;
    for (int kc = 0; kc < C_OUT; kc += KC) {
        load_w_chunk(sW, g_W3t + (size_t)kc * C_OUT, C_OUT, tid);
        const float4* ar = (const float4*)(Ar + kc) + q * 4;
        float2* d = sV2 + row * SVS + q * 16;
#pragma unroll
        for (int j = 0; j < 4; ++j) {
            float4 v = ar[j];
            d[j * 4 + 0] = make_float2(v.x, v.x);
            d[j * 4 + 1] = make_float2(v.y, v.y);
            d[j * 4 + 2] = make_float2(v.z, v.z);
            d[j * 4 + 3] = make_float2(v.w, v.w);
        }
        __syncthreads();
        gemm_chunk(sV2, sW, acc, mg, ng);
        __syncthreads();
    }

    int n0 = ng * 8;
    float b3v[8], s3v[8], t3v[8];
#pragma unroll
    for (int u = 0; u < 8; ++u) {
        b3v[u] = __ldg(&b3[n0 + u]);
        s3v[u] = __ldg(&g_s3[n0 + u]);
        t3v[u] = __ldg(&g_t3[n0 + u]);
    }
#pragma unroll
    for (int i = 0; i < 8; ++i) {
        int nd = m0 + mg * 8 + i;
        if (nd >= Nn) break;
        float* dst = out + (size_t)nd * C_OUT + n0;
#pragma unroll
        for (int p = 0; p < 4; ++p) {
            float2 z = unpack2(acc[i][p]);
            dst[2 * p]     = fmaxf(z.x + b3v[2 * p],     0.0f) * s3v[2 * p]     + t3v[2 * p];
            dst[2 * p + 1] = fmaxf(z.y + b3v[2 * p + 1], 0.0f) * s3v[2 * p + 1] + t3v[2 * p + 1];
        }
    }
}

// ---------------------------------------------------------------------------
extern "C" void kernel_launch(void* const* d_in, const int* in_sizes, int n_in,
                              void* d_out, int out_size) {
    const float* x   = (const float*)d_in[0];
    const void*  idx = (const void*)d_in[1];
    const float* W1 = (const float*)d_in[2];  const float* b1 = (const float*)d_in[3];
    const float* g1 = (const float*)d_in[4];  const float* be1= (const float*)d_in[5];
    const float* m1 = (const float*)d_in[6];  const float* v1 = (const float*)d_in[7];
    const float* W2 = (const float*)d_in[8];  const float* b2 = (const float*)d_in[9];
    const float* g2 = (const float*)d_in[10]; const float* be2= (const float*)d_in[11];
    const float* m2 = (const float*)d_in[12]; const float* v2 = (const float*)d_in[13];
    const float* W3 = (const float*)d_in[14]; const float* b3 = (const float*)d_in[15];
    const float* g3 = (const float*)d_in[16]; const float* be3= (const float*)d_in[17];
    const float* m3 = (const float*)d_in[18]; const float* v3 = (const float*)d_in[19];
    float* out = (float*)d_out;

    int Nn = in_sizes[0] / C_IN;
    long long E2 = (long long)in_sizes[1];
    long long E  = E2 >> 1;
    long long EN = E + Nn;

    size_t shmem13 = (size_t)TM * SVS * sizeof(float2) + (size_t)KC * C_OUT * sizeof(float);
    size_t shmem2  = (size_t)PROW128 * sizeof(float2) + (size_t)KC * C_OUT * sizeof(float);
    cudaFuncSetAttribute(k1_node_gemm, cudaFuncAttributeMaxDynamicSharedMemorySize, (int)shmem13);
    cudaFuncSetAttribute(k2_edge_gemm, cudaFuncAttributeMaxDynamicSharedMemorySize, (int)shmem2);
    cudaFuncSetAttribute(k3_out_gemm,  cudaFuncAttributeMaxDynamicSharedMemorySize, (int)shmem13);

    // decode + counting sort by tgt
    detect_idx<<<1, 32>>>((const int*)idx);
    decode_idx<<<(int)((E2 + 255) / 256), 256>>>(idx, E2, Nn);
    hist_zero<<<(Nn + 255) / 256, 256>>>(Nn);
    hist_tgt<<<(int)((E + 255) / 256), 256>>>(E);
    scan_base<<<1, 256>>>(Nn);
    scatter_edges<<<(int)((E + 255) / 256), 256>>>(E);
    scatter_loops<<<(Nn + 255) / 256, 256>>>(Nn);

    prep_bn<<<1, C_OUT>>>(g1, be1, m1, v1, W2, b2, g2, be2, m2, v2, g3, be3, m3, v3);
    prep_w<<<(C_IN * 2 * C_OUT + 255) / 256, 256>>>(W1, W2, W3, g1, v1);

    int total = Nn * C_OUT;
    init_agg<<<(total + 255) / 256, 256>>>(total);

    dim3 grid1((Nn + TM - 1) / TM, 2);
    k1_node_gemm<<<grid1, NTHR, shmem13>>>(x, b1, Nn);

    int nblk2 = (int)((EN + TM2 - 1) / TM2);
    k2_edge_gemm<<<nblk2, NTHR, shmem2>>>(EN);

    k3_out_gemm<<<(Nn + TM - 1) / TM, NTHR, shmem13>>>(b3, out, Nn);
}